// round 1
// baseline (speedup 1.0000x reference)
#include <cuda_runtime.h>

// GIoU loss mean over N=4,000,000 box pairs.
// HBM-bound streaming reduction: 128 MB in, 4 bytes out.

#define NBLOCKS 1184   // 8 waves of 148 SMs
#define NTHREADS 256

__device__ float g_partials[NBLOCKS];

__global__ __launch_bounds__(NTHREADS)
void giou_main_kernel(const float4* __restrict__ pred,
                      const float4* __restrict__ tgt,
                      int n) {
    float acc = 0.0f;
    const int stride = gridDim.x * blockDim.x;
    for (int i = blockIdx.x * blockDim.x + threadIdx.x; i < n; i += stride) {
        float4 p = __ldg(&pred[i]);   // (x1, y1, x2, y2)
        float4 t = __ldg(&tgt[i]);

        float area_p = (p.z - p.x) * (p.w - p.y);
        float area_t = (t.z - t.x) * (t.w - t.y);

        float iw = fmaxf(fminf(p.z, t.z) - fmaxf(p.x, t.x), 0.0f);
        float ih = fmaxf(fminf(p.w, t.w) - fmaxf(p.y, t.y), 0.0f);
        float inter = iw * ih;
        float uni   = area_p + area_t - inter;
        float iou   = inter / uni;

        float cw = fmaxf(p.z, t.z) - fminf(p.x, t.x);
        float ch = fmaxf(p.w, t.w) - fminf(p.y, t.y);
        float area_c = cw * ch;

        float giou = iou - (area_c - uni) / area_c;
        acc += 1.0f - giou;
    }

    // Warp reduce
    #pragma unroll
    for (int o = 16; o > 0; o >>= 1)
        acc += __shfl_xor_sync(0xffffffffu, acc, o);

    __shared__ float s[NTHREADS / 32];
    if ((threadIdx.x & 31) == 0) s[threadIdx.x >> 5] = acc;
    __syncthreads();

    // First warp reduces the 8 per-warp partials
    if (threadIdx.x < 32) {
        float v = (threadIdx.x < NTHREADS / 32) ? s[threadIdx.x] : 0.0f;
        #pragma unroll
        for (int o = 4; o > 0; o >>= 1)
            v += __shfl_xor_sync(0xffffffffu, v, o);
        if (threadIdx.x == 0) g_partials[blockIdx.x] = v;
    }
}

__global__ __launch_bounds__(1024)
void giou_final_kernel(float* __restrict__ out, float inv_n) {
    float acc = 0.0f;
    for (int i = threadIdx.x; i < NBLOCKS; i += blockDim.x)
        acc += g_partials[i];

    #pragma unroll
    for (int o = 16; o > 0; o >>= 1)
        acc += __shfl_xor_sync(0xffffffffu, acc, o);

    __shared__ float s[32];
    if ((threadIdx.x & 31) == 0) s[threadIdx.x >> 5] = acc;
    __syncthreads();

    if (threadIdx.x < 32) {
        float v = (threadIdx.x < 32) ? s[threadIdx.x] : 0.0f;  // blockDim=1024 -> 32 warps
        #pragma unroll
        for (int o = 16; o > 0; o >>= 1)
            v += __shfl_xor_sync(0xffffffffu, v, o);
        if (threadIdx.x == 0) *out = v * inv_n;
    }
}

extern "C" void kernel_launch(void* const* d_in, const int* in_sizes, int n_in,
                              void* d_out, int out_size) {
    const float4* pred = (const float4*)d_in[0];
    const float4* tgt  = (const float4*)d_in[1];
    float* out = (float*)d_out;

    const int n = in_sizes[0] / 4;   // in_sizes is element count of floats; 4 per box

    giou_main_kernel<<<NBLOCKS, NTHREADS>>>(pred, tgt, n);
    giou_final_kernel<<<1, 1024>>>(out, 1.0f / (float)n);
}